// round 13
// baseline (speedup 1.0000x reference)
#include <cuda_runtime.h>
#include <math.h>

// SO3 projection, reduced from the SVD reference:
//   Rb    = sign(det A) * U_p^T           (U_p = polar factor of A)
//   trans = -sqrt(3) * U_p^T t / ||A||_F  (sign cancels)
// U_p via determinantally-scaled Newton + unscaled Newton.
//
// R13: the kernel's floor is FMA-pipe occupancy (~63% of runtime at
// 6 iterations; everything else is stall fill). Cut to 3 scaled +
// 2 unscaled iterations (-17% FFMA). Quadratic convergence bounds the
// 5-iter error well below the 1e-3 tolerance (6-iter run sat at the
// 2e-7 fp32 floor). zeta = |d|^{-1/3} via exponent bit-hack + 1 Newton
// refinement; izd = 0.5*sign(d)*zeta^2 (no MUFU in scaled iters).
// Layout: R11's best-ncu config (1024x256, 2 serial matrices/thread).

__device__ __forceinline__ void project_one(const float4* __restrict__ in,
                                            float4* __restrict__ out, int b)
{
    float4 r0 = in[4 * b + 0];
    float4 r1 = in[4 * b + 1];
    float4 r2 = in[4 * b + 2];

    float x00 = r0.x, x01 = r0.y, x02 = r0.z, t0 = r0.w;
    float x10 = r1.x, x11 = r1.y, x12 = r1.z, t1 = r1.w;
    float x20 = r2.x, x21 = r2.y, x22 = r2.z, t2 = r2.w;

    float detA = x00 * (x11 * x22 - x12 * x21)
               - x01 * (x10 * x22 - x12 * x20)
               + x02 * (x10 * x21 - x11 * x20);
    float fro2 = x00 * x00 + x01 * x01 + x02 * x02
               + x10 * x10 + x11 * x11 + x12 * x12
               + x20 * x20 + x21 * x21 + x22 * x22;
    float s  = (detA < 0.0f) ? -1.0f : 1.0f;
    float ts = -1.7320508075688772f * rsqrtf(fro2);

    // ---- 3 scaled Newton iterations (MUFU-free zeta) ----
#pragma unroll
    for (int it = 0; it < 3; ++it) {
        float c00 = x11 * x22 - x12 * x21;
        float c01 = x12 * x20 - x10 * x22;
        float c02 = x10 * x21 - x11 * x20;
        float c10 = x02 * x21 - x01 * x22;
        float c11 = x00 * x22 - x02 * x20;
        float c12 = x01 * x20 - x00 * x21;
        float c20 = x01 * x12 - x02 * x11;
        float c21 = x02 * x10 - x00 * x12;
        float c22 = x00 * x11 - x01 * x10;
        float d   = x00 * c00 + x01 * c01 + x02 * c02;

        float ad = fmaxf(fabsf(d), 1e-30f);

        // zeta ~= ad^{-1/3}: exponent hack + one Newton refinement
        float y  = __int_as_float((int)(0x54AAAAAAu -
                     (unsigned)__float_as_int(ad) / 3u));
        float y2 = y * y;
        float tq = ad * (y2 * y2);
        y = 1.33333333f * y - 0.33333333f * tq;

        float hz  = 0.5f * y;
        float izd = copysignf(0.5f * y * y, d);

        x00 = hz * x00 + izd * c00;
        x01 = hz * x01 + izd * c01;
        x02 = hz * x02 + izd * c02;
        x10 = hz * x10 + izd * c10;
        x11 = hz * x11 + izd * c11;
        x12 = hz * x12 + izd * c12;
        x20 = hz * x20 + izd * c20;
        x21 = hz * x21 + izd * c21;
        x22 = hz * x22 + izd * c22;
    }

    // ---- 2 unscaled Newton iterations ----
#pragma unroll
    for (int it = 0; it < 2; ++it) {
        float c00 = x11 * x22 - x12 * x21;
        float c01 = x12 * x20 - x10 * x22;
        float c02 = x10 * x21 - x11 * x20;
        float c10 = x02 * x21 - x01 * x22;
        float c11 = x00 * x22 - x02 * x20;
        float c12 = x01 * x20 - x00 * x21;
        float c20 = x01 * x12 - x02 * x11;
        float c21 = x02 * x10 - x00 * x12;
        float c22 = x00 * x11 - x01 * x10;
        float d   = x00 * c00 + x01 * c01 + x02 * c02;

        float izd = __fdividef(0.5f, d);

        x00 = 0.5f * x00 + izd * c00;
        x01 = 0.5f * x01 + izd * c01;
        x02 = 0.5f * x02 + izd * c02;
        x10 = 0.5f * x10 + izd * c10;
        x11 = 0.5f * x11 + izd * c11;
        x12 = 0.5f * x12 + izd * c12;
        x20 = 0.5f * x20 + izd * c20;
        x21 = 0.5f * x21 + izd * c21;
        x22 = 0.5f * x22 + izd * c22;
    }

    // Emit: Rb = s * X^T, trans_i = ts * (col_i(X) . t), row3 = e3
    float tr0 = ts * (x00 * t0 + x10 * t1 + x20 * t2);
    float tr1 = ts * (x01 * t0 + x11 * t1 + x21 * t2);
    float tr2 = ts * (x02 * t0 + x12 * t1 + x22 * t2);

    float4* o = out + 4 * b;
    __stcs(o + 0, make_float4(s * x00, s * x10, s * x20, tr0));
    __stcs(o + 1, make_float4(s * x01, s * x11, s * x21, tr1));
    __stcs(o + 2, make_float4(s * x02, s * x12, s * x22, tr2));
    __stcs(o + 3, make_float4(0.0f, 0.0f, 0.0f, 1.0f));
}

__global__ void __launch_bounds__(256, 8)   // 32-reg cap (proven spill-free)
so3_project_kernel(const float4* __restrict__ in, float4* __restrict__ out,
                   int n, int half)
{
    int tid = blockIdx.x * blockDim.x + threadIdx.x;
    if (tid >= half) return;

    project_one(in, out, tid);
    int b2 = tid + half;
    if (b2 < n) project_one(in, out, b2);
}

extern "C" void kernel_launch(void* const* d_in, const int* in_sizes, int n_in,
                              void* d_out, int out_size)
{
    const int n    = in_sizes[0] / 16;       // 524288 matrices
    const int half = (n + 1) / 2;            // 262144 threads, 2 matrices each
    const int threads = 256;
    const int blocks  = (half + threads - 1) / threads;   // 1024 CTAs: 1 wave
    so3_project_kernel<<<blocks, threads>>>(
        (const float4*)d_in[0], (float4*)d_out, n, half);
}

// round 14
// speedup vs baseline: 1.1577x; 1.1577x over previous
#include <cuda_runtime.h>
#include <math.h>

// SO3 projection, reduced from the SVD reference:
//   Rb    = sign(det A) * U_p^T           (U_p = polar factor of A)
//   trans = -sqrt(3) * U_p^T t / ||A||_F  (sign cancels)
// U_p via determinantally-scaled Newton (3) + unscaled Newton (2);
// rel_err ~1.6e-5 (validated R13), tolerance 1e-3.
//
// R14: bench-optimal family (flat 1 matrix/thread, 2048x256, PLAIN
// stores -- __stcs variants consistently bench ~2us worse across
// graph replays, likely L2 output-line eviction between replays).
// Math shaves: sign(detA) taken from iteration 1's det (the separate
// detA computation duplicated those 11 ops); final sign multiply
// folded into the last iteration's coefficients (emit sX directly,
// compensate ts <- s*ts since s^2 = 1).

__global__ void __launch_bounds__(256, 8)   // 32-reg cap (proven spill-free)
so3_project_kernel(const float4* __restrict__ in, float4* __restrict__ out, int n)
{
    int b = blockIdx.x * blockDim.x + threadIdx.x;
    if (b >= n) return;

    float4 r0 = in[4 * b + 0];
    float4 r1 = in[4 * b + 1];
    float4 r2 = in[4 * b + 2];

    float x00 = r0.x, x01 = r0.y, x02 = r0.z, t0 = r0.w;
    float x10 = r1.x, x11 = r1.y, x12 = r1.z, t1 = r1.w;
    float x20 = r2.x, x21 = r2.y, x22 = r2.z, t2 = r2.w;

    float fro2 = x00 * x00 + x01 * x01 + x02 * x02
               + x10 * x10 + x11 * x11 + x12 * x12
               + x20 * x20 + x21 * x21 + x22 * x22;
    float ts = -1.7320508075688772f * rsqrtf(fro2);
    float s  = 1.0f;   // set from iteration 0's det (det(A) sign)

    // ---- 3 scaled Newton iterations (MUFU-free zeta) ----
#pragma unroll
    for (int it = 0; it < 3; ++it) {
        float c00 = x11 * x22 - x12 * x21;
        float c01 = x12 * x20 - x10 * x22;
        float c02 = x10 * x21 - x11 * x20;
        float c10 = x02 * x21 - x01 * x22;
        float c11 = x00 * x22 - x02 * x20;
        float c12 = x01 * x20 - x00 * x21;
        float c20 = x01 * x12 - x02 * x11;
        float c21 = x02 * x10 - x00 * x12;
        float c22 = x00 * x11 - x01 * x10;
        float d   = x00 * c00 + x01 * c01 + x02 * c02;

        if (it == 0)                          // X == A here: d == det(A)
            s = (d < 0.0f) ? -1.0f : 1.0f;

        float ad = fmaxf(fabsf(d), 1e-30f);

        // zeta ~= ad^{-1/3}: exponent hack + one Newton refinement
        float y  = __int_as_float((int)(0x54AAAAAAu -
                     (unsigned)__float_as_int(ad) / 3u));
        float y2 = y * y;
        float tq = ad * (y2 * y2);
        y = 1.33333333f * y - 0.33333333f * tq;

        float hz  = 0.5f * y;
        float izd = copysignf(hz * y, d);     // 0.5*sign(d)*zeta^2

        x00 = hz * x00 + izd * c00;
        x01 = hz * x01 + izd * c01;
        x02 = hz * x02 + izd * c02;
        x10 = hz * x10 + izd * c10;
        x11 = hz * x11 + izd * c11;
        x12 = hz * x12 + izd * c12;
        x20 = hz * x20 + izd * c20;
        x21 = hz * x21 + izd * c21;
        x22 = hz * x22 + izd * c22;
    }

    // ---- 2 unscaled Newton iterations; fold s into the LAST one ----
#pragma unroll
    for (int it = 0; it < 2; ++it) {
        float c00 = x11 * x22 - x12 * x21;
        float c01 = x12 * x20 - x10 * x22;
        float c02 = x10 * x21 - x11 * x20;
        float c10 = x02 * x21 - x01 * x22;
        float c11 = x00 * x22 - x02 * x20;
        float c12 = x01 * x20 - x00 * x21;
        float c20 = x01 * x12 - x02 * x11;
        float c21 = x02 * x10 - x00 * x12;
        float c22 = x00 * x11 - x01 * x10;
        float d   = x00 * c00 + x01 * c01 + x02 * c02;

        float g   = (it == 1) ? 0.5f * s : 0.5f;   // scale final X by s
        float izd = __fdividef(g, d);

        x00 = g * x00 + izd * c00;
        x01 = g * x01 + izd * c01;
        x02 = g * x02 + izd * c02;
        x10 = g * x10 + izd * c10;
        x11 = g * x11 + izd * c11;
        x12 = g * x12 + izd * c12;
        x20 = g * x20 + izd * c20;
        x21 = g * x21 + izd * c21;
        x22 = g * x22 + izd * c22;
    }

    // X now holds s*U_p. Rb = X^T (rows = columns of X).
    // trans = ts * U_p^T t = (s*ts) * X^T t   (s^2 = 1)
    float tss = s * ts;
    float tr0 = tss * (x00 * t0 + x10 * t1 + x20 * t2);
    float tr1 = tss * (x01 * t0 + x11 * t1 + x21 * t2);
    float tr2 = tss * (x02 * t0 + x12 * t1 + x22 * t2);

    out[4 * b + 0] = make_float4(x00, x10, x20, tr0);
    out[4 * b + 1] = make_float4(x01, x11, x21, tr1);
    out[4 * b + 2] = make_float4(x02, x12, x22, tr2);
    out[4 * b + 3] = make_float4(0.0f, 0.0f, 0.0f, 1.0f);
}

extern "C" void kernel_launch(void* const* d_in, const int* in_sizes, int n_in,
                              void* d_out, int out_size)
{
    const int n = in_sizes[0] / 16;
    const int threads = 256;
    const int blocks  = (n + threads - 1) / threads;
    so3_project_kernel<<<blocks, threads>>>(
        (const float4*)d_in[0], (float4*)d_out, n);
}